// round 16
// baseline (speedup 1.0000x reference)
#include <cuda_runtime.h>
#include <cuda_bf16.h>
#include <mma.h>
#include <math.h>

using namespace nvcuda;

#define BB 4
#define SS 1024
#define DD 1024
#define HH 16
#define DKK 64
#define NBE (BB * SS * DD)   // 4M elems
#define NWE (DD * DD)        // 1M elems

typedef __nv_bfloat16 bf16;

// ---------------- scratch (device globals) ----------------------------------
__device__ float g_cs [67108864];
__device__ float g_c2 [67108864];
__device__ float g_bu [BB * HH * SS];
__device__ float g_bv [HH * SS];
__device__ bf16 g_x3h[3 * NBE], g_x3l[3 * NBE];
__device__ bf16 g_W3h[3 * NWE], g_W3l[3 * NWE];
__device__ bf16 g_Wph[NWE], g_Wpl[NWE];
__device__ bf16 g_Woh[NWE], g_Wol[NWE];
__device__ bf16 g_peh[SS * DD], g_pel[SS * DD];
__device__ bf16 g_o3h[3 * NBE], g_o3l[3 * NBE];
__device__ bf16 g_pph[SS * DD], g_ppl[SS * DD];
__device__ bf16 g_ath[67108864], g_atl[67108864];
__device__ bf16 g_cxh[NBE], g_cxl[NBE];

__device__ __forceinline__ unsigned su32(const void* p) {
    return (unsigned)__cvta_generic_to_shared(p);
}
__device__ __forceinline__ void cp16(unsigned saddr, const void* g) {
    asm volatile("cp.async.cg.shared.global [%0], [%1], 16;" :: "r"(saddr), "l"(g));
}

// ---------------- batched elementwise splits ----------------------------------
__global__ void split_in3(const float* __restrict__ q, const float* __restrict__ k,
                          const float* __restrict__ v,
                          bf16* __restrict__ hi, bf16* __restrict__ lo) {
    const int n4 = NBE / 4;
    int i = blockIdx.x * blockDim.x + threadIdx.x;
    if (i >= 3 * n4) return;
    const float* src = (i < n4) ? q : (i < 2 * n4 ? k : v);
    int li = i - (i < n4 ? 0 : (i < 2 * n4 ? n4 : 2 * n4));
    float4 fv = ((const float4*)src)[li];
    float f[4] = {fv.x, fv.y, fv.z, fv.w};
    bf16 h[4], l[4];
    #pragma unroll
    for (int t = 0; t < 4; t++) {
        h[t] = __float2bfloat16(f[t]);
        l[t] = __float2bfloat16(f[t] - __bfloat162float(h[t]));
    }
    ((uint2*)hi)[i] = *(uint2*)h;
    ((uint2*)lo)[i] = *(uint2*)l;
}

__global__ void split_w5(const float* __restrict__ wq, const float* __restrict__ wk,
                         const float* __restrict__ wv, const float* __restrict__ wp,
                         const float* __restrict__ wo,
                         bf16* __restrict__ w3h, bf16* __restrict__ w3l,
                         bf16* __restrict__ wph, bf16* __restrict__ wpl,
                         bf16* __restrict__ woh, bf16* __restrict__ wol) {
    const int n4 = NWE / 4;
    int i = blockIdx.x * blockDim.x + threadIdx.x;
    if (i >= 5 * n4) return;
    int sel = i / n4, li = i - sel * n4;
    const float* src;  bf16* hi;  bf16* lo;  int oi;
    switch (sel) {
        case 0: src = wq; hi = w3h; lo = w3l; oi = li;          break;
        case 1: src = wk; hi = w3h; lo = w3l; oi = li + n4;     break;
        case 2: src = wv; hi = w3h; lo = w3l; oi = li + 2 * n4; break;
        case 3: src = wp; hi = wph; lo = wpl; oi = li;          break;
        default:src = wo; hi = woh; lo = wol; oi = li;          break;
    }
    float4 fv = ((const float4*)src)[li];
    float f[4] = {fv.x, fv.y, fv.z, fv.w};
    bf16 h[4], l[4];
    #pragma unroll
    for (int t = 0; t < 4; t++) {
        h[t] = __float2bfloat16(f[t]);
        l[t] = __float2bfloat16(f[t] - __bfloat162float(h[t]));
    }
    ((uint2*)hi)[oi] = *(uint2*)h;
    ((uint2*)lo)[oi] = *(uint2*)l;
}

// ---------------- pos emb -----------------------------------------------------
__global__ void posemb_kernel(bf16* __restrict__ peh, bf16* __restrict__ pel) {
    int idx = blockIdx.x * blockDim.x + threadIdx.x;
    if (idx >= SS * (DD / 2)) return;
    int j = idx / (DD / 2);
    int i = idx - j * (DD / 2);
    float t = (2.0f * (float)i) / (float)DD;
    float invf = expf(-t * 9.210340371976184f);
    float pos = (float)(SS - 1 - j);
    float s, c;
    sincosf(pos * invf, &s, &c);
    bf16 sh = __float2bfloat16(s);
    bf16 ch = __float2bfloat16(c);
    peh[j * DD + i]          = sh;
    pel[j * DD + i]          = __float2bfloat16(s - __bfloat162float(sh));
    peh[j * DD + i + DD / 2] = ch;
    pel[j * DD + i + DD / 2] = __float2bfloat16(c - __bfloat162float(ch));
}

// ---------------- fused bias vectors -------------------------------------------
__global__ void bias_fused(const bf16* __restrict__ kh, const bf16* __restrict__ kl,
                           const bf16* __restrict__ ph, const bf16* __restrict__ pl,
                           const float* __restrict__ u, const float* __restrict__ vb,
                           float* __restrict__ bu, float* __restrict__ bv) {
    int gw   = (blockIdx.x * blockDim.x + threadIdx.x) >> 5;
    int lane = threadIdx.x & 31;
    const int NBU = BB * HH * SS;
    if (gw >= NBU + HH * SS) return;
    const bf16 *sh, *sl; const float* w; long base; float* dst; int di;
    if (gw < NBU) {
        int kk = gw % SS;
        int h  = (gw / SS) % HH;
        int b  = gw / (SS * HH);
        sh = kh; sl = kl; w = u + h * DKK;
        base = ((long)b * SS + kk) * DD + h * DKK;
        dst = bu; di = gw;
    } else {
        int g2 = gw - NBU;
        int j = g2 % SS;
        int h = g2 / SS;
        sh = ph; sl = pl; w = vb + h * DKK;
        base = (long)j * DD + h * DKK;
        dst = bv; di = g2;
    }
    float x0 = __bfloat162float(sh[base + lane])      + __bfloat162float(sl[base + lane]);
    float x1 = __bfloat162float(sh[base + lane + 32]) + __bfloat162float(sl[base + lane + 32]);
    float s = x0 * w[lane] + x1 * w[lane + 32];
    #pragma unroll
    for (int o = 16; o; o >>= 1) s += __shfl_xor_sync(0xffffffffu, s, o);
    if (lane == 0) dst[di] = s;
}

// ---------------- NT GEMM, cp.async 3-stage pipeline (R10-validated) ---------
// zAux: fused aux problem. zSplit: second score GEMM. biasM/biasS: optional
// column-bias added in epilogue (main / split halves respectively).
#define NT_ARR_E   (128 * 24)
#define NT_STAGE_E (4 * NT_ARR_E)
#define NT_SMEM    (3 * NT_STAGE_E * 2)  // 73728 bytes

template<bool SPLIT>
__global__ __launch_bounds__(256, 2) void gemm_nt_s(
    const bf16* __restrict__ Ahg, const bf16* __restrict__ Alg,
    const bf16* __restrict__ Bhg, const bf16* __restrict__ Blg,
    float* __restrict__ C, bf16* __restrict__ Ch, bf16* __restrict__ Cl,
    int K, int lda, int ldb, int ldc,
    int Hdim, long strAb, long strAh, long strBb, long strBh, long strCb, long strCh,
    int zAux, int mAux,
    const bf16* A2h, const bf16* A2l, const bf16* B2h, const bf16* B2l,
    bf16* C2h, bf16* C2l,
    int zSplit, const bf16* Bsh, const bf16* Bsl, float* Csf,
    const float* biasM, const float* biasS)
{
    int z = blockIdx.z;
    long coff;
    const float* bias = nullptr;
    if (zAux >= 0 && z == zAux) {
        if (blockIdx.y >= mAux) return;
        Ahg = A2h;  Alg = A2l;  Bhg = B2h;  Blg = B2l;
        Ch  = C2h;  Cl  = C2l;  C = nullptr;
        coff = 0;
    } else {
        long sBb = strBb;
        const float* bsel = biasM;
        if (z >= zSplit) {
            z -= zSplit;
            Bhg = Bsh;  Blg = Bsl;  C = Csf;
            sBb = 0;
            bsel = nullptr;   // set below from biasS with h index
        }
        int bb = z / Hdim, hh = z - bb * Hdim;
        Ahg += bb * strAb + hh * strAh;  Alg += bb * strAb + hh * strAh;
        Bhg += bb * sBb + hh * strBh;    Blg += bb * sBb + hh * strBh;
        coff = bb * strCb + hh * strCh;
        if (bsel)                       bias = bsel + (long)(bb * Hdim + hh) * ldc;
        else if (blockIdx.z >= zSplit && zSplit < (1 << 29) && biasS)
                                        bias = biasS + (long)hh * ldc;
    }

    extern __shared__ __align__(16) bf16 smem[];

    const int tid  = threadIdx.x;
    const int m0   = blockIdx.y * 128;
    const int n0   = blockIdx.x * 128;
    const int lrow = tid >> 1;
    const int lc8  = (tid & 1) * 8;
    const int w    = tid >> 5;
    const int wm   = w >> 2;
    const int wn   = w & 3;

    const bf16* ah = Ahg + (long)(m0 + lrow) * lda + lc8;
    const bf16* al = Alg + (long)(m0 + lrow) * lda + lc8;
    const bf16* bh = Bhg + (long)(n0 + lrow) * ldb + lc8;
    const bf16* bl = Blg + (long)(n0 + lrow) * ldb + lc8;

    const unsigned sbase = su32(smem) + (unsigned)(lrow * 24 + lc8) * 2u;

    wmma::fragment<wmma::accumulator, 16, 16, 16, float> acc[4][2];
    #pragma unroll
    for (int i = 0; i < 4; i++)
        #pragma unroll
        for (int j = 0; j < 2; j++) wmma::fill_fragment(acc[i][j], 0.0f);

    const int nt = K / 16;

    auto load_stage = [&](int buf, int kt) {
        const unsigned so = sbase + (unsigned)(buf * NT_STAGE_E) * 2u;
        const int k0 = kt * 16;
        cp16(so,                       ah + k0);
        cp16(so + NT_ARR_E * 2u,       al + k0);
        cp16(so + 2u * NT_ARR_E * 2u,  bh + k0);
        cp16(so + 3u * NT_ARR_E * 2u,  bl + k0);
        asm volatile("cp.async.commit_group;" ::: "memory");
    };

    load_stage(0, 0);
    if (nt > 1) load_stage(1, 1);
    if (nt > 2) load_stage(2, 2);

    for (int kt = 0; kt < nt; kt++) {
        const int buf = kt % 3;
        const int rem = nt - kt - 1;
        if (rem >= 2)      asm volatile("cp.async.wait_group 2;" ::: "memory");
        else if (rem == 1) asm volatile("cp.async.wait_group 1;" ::: "memory");
        else               asm volatile("cp.async.wait_group 0;" ::: "memory");
        __syncthreads();

        bf16* sc = smem + buf * NT_STAGE_E;
        {
            wmma::fragment<wmma::matrix_a, 16, 16, 16, bf16, wmma::row_major> fa[4];
            wmma::fragment<wmma::matrix_b, 16, 16, 16, bf16, wmma::col_major> fbh[2], fbl[2];
            #pragma unroll
            for (int i = 0; i < 4; i++)
                wmma::load_matrix_sync(fa[i], &sc[(wm * 64 + i * 16) * 24], 24);
            #pragma unroll
            for (int j = 0; j < 2; j++) {
                wmma::load_matrix_sync(fbh[j], &sc[2 * NT_ARR_E + (wn * 32 + j * 16) * 24], 24);
                wmma::load_matrix_sync(fbl[j], &sc[3 * NT_ARR_E + (wn * 32 + j * 16) * 24], 24);
            }
            #pragma unroll
            for (int i = 0; i < 4; i++)
                #pragma unroll
                for (int j = 0; j < 2; j++) {
                    wmma::mma_sync(acc[i][j], fa[i], fbh[j], acc[i][j]);
                    wmma::mma_sync(acc[i][j], fa[i], fbl[j], acc[i][j]);
                }
            #pragma unroll
            for (int i = 0; i < 4; i++)
                wmma::load_matrix_sync(fa[i], &sc[NT_ARR_E + (wm * 64 + i * 16) * 24], 24);
            #pragma unroll
            for (int i = 0; i < 4; i++)
                #pragma unroll
                for (int j = 0; j < 2; j++)
                    wmma::mma_sync(acc[i][j], fa[i], fbh[j], acc[i][j]);
        }
        __syncthreads();
        if (kt + 3 < nt) load_stage(buf, kt + 3);
    }

    if constexpr (!SPLIT) {
        float* Co = C + coff;
        if (bias == nullptr) {
            #pragma unroll
            for (int i = 0; i < 4; i++)
                #pragma unroll
                for (int j = 0; j < 2; j++)
                    wmma::store_matrix_sync(Co + (long)(m0 + wm * 64 + i * 16) * ldc + n0 + wn * 32 + j * 16,
                                            acc[i][j], ldc, wmma::mem_row_major);
        } else {
            // staged epilogue adding column bias (pipeline drained; reuse smem)
            float* stg = (float*)smem + w * 16 * 20;
            const int lane = tid & 31;
            const int rr  = lane >> 1;
            const int c8  = (lane & 1) * 8;
            #pragma unroll
            for (int i = 0; i < 4; i++)
                #pragma unroll
                for (int j = 0; j < 2; j++) {
                    __syncwarp();
                    wmma::store_matrix_sync(stg, acc[i][j], 20, wmma::mem_row_major);
                    __syncwarp();
                    const int colb = n0 + wn * 32 + j * 16 + c8;
                    float4 b0 = *(const float4*)(bias + colb);
                    float4 b1 = *(const float4*)(bias + colb + 4);
                    long off = (long)(m0 + wm * 64 + i * 16 + rr) * ldc + colb;
                    float* s = stg + rr * 20 + c8;
                    *(float4*)(Co + off)     = make_float4(s[0] + b0.x, s[1] + b0.y,
                                                           s[2] + b0.z, s[3] + b0.w);
                    *(float4*)(Co + off + 4) = make_float4(s[4] + b1.x, s[5] + b1.y,
                                                           s[6] + b1.z, s[7] + b1.w);
                }
        }
    } else {
        float* stg = (float*)smem + w * 16 * 20;   // drained pipeline smem
        bf16* Hh = Ch + coff;
        bf16* Ll = Cl + coff;
        const int lane = tid & 31;
        const int rr  = lane >> 1;
        const int c8  = (lane & 1) * 8;
        #pragma unroll
        for (int i = 0; i < 4; i++)
            #pragma unroll
            for (int j = 0; j < 2; j++) {
                __syncwarp();
                wmma::store_matrix_sync(stg, acc[i][j], 20, wmma::mem_row_major);
                __syncwarp();
                bf16 hv[8], lv[8];
                #pragma unroll
                for (int e = 0; e < 8; e++) {
                    float v = stg[rr * 20 + c8 + e];
                    hv[e] = __float2bfloat16(v);
                    lv[e] = __float2bfloat16(v - __bfloat162float(hv[e]));
                }
                long off = (long)(m0 + wm * 64 + i * 16 + rr) * ldc + n0 + wn * 32 + j * 16 + c8;
                *(uint4*)(Hh + off) = *(uint4*)hv;
                *(uint4*)(Ll + off) = *(uint4*)lv;
            }
    }
}

// ---------------- NN GEMM N=64, cp.async 3-stage pipeline --------------------
#define NN_A_E     (128 * 24)
#define NN_B_E     (16 * 72)
#define NN_STAGE_E (2 * NN_A_E + 2 * NN_B_E)
#define NN_SMEM    (3 * NN_STAGE_E * 2)          // 50688 bytes

template<bool SPLIT>
__global__ __launch_bounds__(256, 2) void gemm_nn64_p(
    const bf16* __restrict__ Ahg, const bf16* __restrict__ Alg,
    const bf16* __restrict__ Bhg, const bf16* __restrict__ Blg,
    float* __restrict__ C, bf16* __restrict__ Ch, bf16* __restrict__ Cl,
    int K, int lda, int ldb, int ldc,
    int Hdim, long strAb, long strAh, long strBb, long strBh, long strCb, long strCh)
{
    int z  = blockIdx.z;
    int bb = z / Hdim, hh = z - bb * Hdim;
    Ahg += bb * strAb + hh * strAh;  Alg += bb * strAb + hh * strAh;
    Bhg += bb * strBb + hh * strBh;  Blg += bb * strBb + hh * strBh;
    long coff = bb * strCb + hh * strCh;

    extern __shared__ __align__(16) bf16 smem[];

    const int tid  = threadIdx.x;
    const int m0   = blockIdx.y * 128;
    const int lrow = tid >> 1;
    const int lc8  = (tid & 1) * 8;
    const int brow = tid >> 3;
    const int bc8  = (tid & 7) * 8;
    const int w    = tid >> 5;
    const int wm   = w >> 1;
    const int wn   = w & 1;

    const bf16* ah = Ahg + (long)(m0 + lrow) * lda + lc8;
    const bf16* al = Alg + (long)(m0 + lrow) * lda + lc8;
    const bf16* bh = Bhg + (long)brow * ldb + bc8;
    const bf16* bl = Blg + (long)brow * ldb + bc8;

    const unsigned saA = su32(smem) + (unsigned)(lrow * 24 + lc8) * 2u;
    const unsigned saB = su32(smem) + (unsigned)(2 * NN_A_E + brow * 72 + bc8) * 2u;
    const bool doB = (tid < 128);

    wmma::fragment<wmma::accumulator, 16, 16, 16, float> acc[2][2];
    #pragma unroll
    for (int i = 0; i < 2; i++)
        #pragma unroll
        for (int j = 0; j < 2; j++) wmma::fill_fragment(acc[i][j], 0.0f);

    const int nt = K / 16;

    auto load_stage = [&](int buf, int kt) {
        const unsigned off = (unsigned)(buf * NN_STAGE_E) * 2u;
        const long k0 = (long)kt * 16;
        cp16(saA + off,                 ah + k0);
        cp16(saA + off + NN_A_E * 2u,   al + k0);
        if (doB) {
            cp16(saB + off,               bh + k0 * ldb);
            cp16(saB + off + NN_B_E * 2u, bl + k0 * ldb);
        }
        asm volatile("cp.async.commit_group;" ::: "memory");
    };

    load_stage(0, 0);
    if (nt > 1) load_stage(1, 1);
    if (nt > 2) load_stage(2, 2);

    for (int kt = 0; kt < nt; kt++) {
        const int buf = kt % 3;
        const int rem = nt - kt - 1;
        if (rem >= 2)      asm volatile("cp.async.wait_group 2;" ::: "memory");
        else if (rem == 1) asm volatile("cp.async.wait_group 1;" ::: "memory");
        else               asm volatile("cp.async.wait_group 0;" ::: "memory");
        __syncthreads();

        bf16* sc  = smem + buf * NN_STAGE_E;
        bf16* scB = sc + 2 * NN_A_E;
        {
            wmma::fragment<wmma::matrix_a, 16, 16, 16, bf16, wmma::row_major> fa[2];
            wmma::fragment<wmma::matrix_b, 16, 16, 16, bf16, wmma::row_major> fbh[2], fbl[2];
            #pragma unroll
            for (int i = 0; i < 2; i++)
                wmma::load_matrix_sync(fa[i], &sc[(wm * 32 + i * 16) * 24], 24);
            #pragma unroll
            for (int j = 0; j < 2; j++) {
                wmma::load_matrix_sync(fbh[j], &scB[wn * 32 + j * 16], 72);
                wmma::load_matrix_sync(fbl[j], &scB[NN_B_E + wn * 32 + j * 16], 72);
            }
            #pragma unroll
            for (int i = 0; i < 2; i++)
                #pragma unroll
                for (int j = 0; j < 2; j++) {
                    wmma::mma_sync(acc[i][j], fa[i], fbh[j], acc[i][j]);
                    wmma::mma_sync(acc[i][j], fa[i], fbl[j], acc[i][j]);
                }
            #pragma unroll
            for (int i = 0; i < 2; i++)
                wmma::load_matrix_sync(fa[i], &sc[NN_A_E + (wm * 32 + i * 16) * 24], 24);
            #pragma unroll
            for (int i = 0; i < 2; i++)
                #pragma unroll
                for (int j = 0; j < 2; j++)
                    wmma::mma_sync(acc[i][j], fa[i], fbh[j], acc[i][j]);
        }
        __syncthreads();
        if (kt + 3 < nt) load_stage(buf, kt + 3);
    }

    if constexpr (!SPLIT) {
        float* Co = C + coff;
        #pragma unroll
        for (int i = 0; i < 2; i++)
            #pragma unroll
            for (int j = 0; j < 2; j++)
                wmma::store_matrix_sync(Co + (long)(m0 + wm * 32 + i * 16) * ldc + wn * 32 + j * 16,
                                        acc[i][j], ldc, wmma::mem_row_major);
    } else {
        float* stg = (float*)smem + w * 16 * 20;
        bf16* Hh = Ch + coff;
        bf16* Ll = Cl + coff;
        const int lane = tid & 31;
        const int rr  = lane >> 1;
        const int c8  = (lane & 1) * 8;
        #pragma unroll
        for (int i = 0; i < 2; i++)
            #pragma unroll
            for (int j = 0; j < 2; j++) {
                __syncwarp();
                wmma::store_matrix_sync(stg, acc[i][j], 20, wmma::mem_row_major);
                __syncwarp();
                bf16 hv[8], lv[8];
                #pragma unroll
                for (int e = 0; e < 8; e++) {
                    float v = stg[rr * 20 + c8 + e];
                    hv[e] = __float2bfloat16(v);
                    lv[e] = __float2bfloat16(v - __bfloat162float(hv[e]));
                }
                long off = (long)(m0 + wm * 32 + i * 16 + rr) * ldc + wn * 32 + j * 16 + c8;
                *(uint4*)(Hh + off) = *(uint4*)hv;
                *(uint4*)(Ll + off) = *(uint4*)lv;
            }
    }
}

// ---------------- shift + softmax (biases pre-folded into cs/c2) -------------
// Thread t handles 4 consecutive columns 4t..4t+3. float4 cs load, coalesced
// c2 gather, packed uint2 bf16 stores.
__global__ __launch_bounds__(256) void softmax_combine(
    const float* __restrict__ cs, const float* __restrict__ c2,
    bf16* __restrict__ ath, bf16* __restrict__ atl)
{
    const int q = blockIdx.x, h = blockIdx.y, b = blockIdx.z;
    const long base = ((long)(b * HH + h) * SS + q) * SS;
    const float* csrow = cs + base;
    const float* psq   = c2 + base;
    const int    q1    = (q + 1 < SS) ? (q + 1) : (SS - 1);
    const float* psq1  = c2 + ((long)(b * HH + h) * SS + q1) * SS;

    const int tid = threadIdx.x;
    const int c0  = tid * 4;

    float4 cv = *(const float4*)(csrow + c0);
    float cva[4] = {cv.x, cv.y, cv.z, cv.w};
    float vals[4];
    float mx = -1e30f;
    #pragma unroll
    for (int e = 0; e < 4; e++) {
        int c = c0 + e;
        float ps;
        if (c <= q)            ps = psq[SS - 1 - q + c];
        else if (c == q + 1)   ps = 0.0f;
        else                   ps = psq1[c - q - 2];
        float s = (cva[e] + ps) * 0.125f;
        vals[e] = s;
        mx = fmaxf(mx, s);
    }

    __shared__ float red[8];
    #pragma unroll
    for (int o = 16; o; o >>= 1) mx = fmaxf(mx, __shfl_xor_sync(0xffffffffu, mx, o));
    if ((tid & 31) == 0) red[tid >> 5] = mx;
    __syncthreads();
    if (tid < 32) {
        float m = (tid < 8) ? red[tid] : -1e30f;
        #pragma unroll
        for (int o = 16; o; o >>= 1) m = fmaxf(m, __shfl_xor_sync(0xffffffffu, m, o));
        if (tid == 0) red[0] = m;
    }
    __syncthreads();
    mx = red[0];

    float sum = 0.0f;
    #pragma unroll
    for (int e = 0; e < 4; e++) { vals[e] = __expf(vals[e] - mx); sum += vals[e]; }

    __shared__ float red2[8];
    #pragma unroll
    for (int o = 16; o; o >>= 1) sum += __shfl_xor_sync(0xffffffffu, sum, o);
    if ((tid & 31) == 0) red2[tid >> 5] = sum;
    __syncthreads();
    if (tid < 32) {
        float s = (tid < 8) ? red2[tid] : 0.0f;
        #pragma unroll
        for (int o = 16; o; o >>= 1) s += __shfl_xor_sync(0xffffffffu, s, o);
        if (tid == 0) red2[0] = s;
    }
    __syncthreads();
    const float inv = 1.0f / red2[0];

    bf16 hv[4], lv[4];
    #pragma unroll
    for (int e = 0; e < 4; e++) {
        float p = vals[e] * inv;
        hv[e] = __float2bfloat16(p);
        lv[e] = __float2bfloat16(p - __bfloat162float(hv[e]));
    }
    *(uint2*)(ath + base + c0) = *(uint2*)hv;
    *(uint2*)(atl + base + c0) = *(uint2*)lv;
}

// ---------------- launch -------------------------------------------------------
extern "C" void kernel_launch(void* const* d_in, const int* in_sizes, int n_in,
                              void* d_out, int out_size)
{
    const float* query = (const float*)d_in[0];
    const float* key   = (const float*)d_in[1];
    const float* value = (const float*)d_in[2];
    // d_in[3] = mask (all-true; no-op)
    const float* Wq = (const float*)d_in[4];
    const float* Wk = (const float*)d_in[5];
    const float* Wv = (const float*)d_in[6];
    const float* Wp = (const float*)d_in[7];
    const float* Wo = (const float*)d_in[8];
    const float* pu = (const float*)d_in[9];
    const float* pv = (const float*)d_in[10];
    float* out = (float*)d_out;

    float *pcs, *pc2, *pbu, *pbv;
    cudaGetSymbolAddress((void**)&pcs,  g_cs);
    cudaGetSymbolAddress((void**)&pc2,  g_c2);
    cudaGetSymbolAddress((void**)&pbu,  g_bu);
    cudaGetSymbolAddress((void**)&pbv,  g_bv);

    bf16 *x3h,*x3l,*W3h,*W3l,*Wph,*Wpl,*Woh,*Wol,*peh,*pel,*o3h,*o3l,*pph,*ppl,*ath,*atl,*cxh,*cxl;
    cudaGetSymbolAddress((void**)&x3h, g_x3h); cudaGetSymbolAddress((void**)&x3l, g_x3l);
    cudaGetSymbolAddress((void**)&W3h, g_W3h); cudaGetSymbolAddress((void**)&W3l, g_W3l);
    cudaGetSymbolAddress((void**)&Wph, g_Wph); cudaGetSymbolAddress((void**)&Wpl, g_Wpl);
    cudaGetSymbolAddress((void**)&Woh, g_Woh); cudaGetSymbolAddress((void**)&Wol, g_Wol);
    cudaGetSymbolAddress((void**)&peh, g_peh); cudaGetSymbolAddress((void**)&pel, g_pel);
    cudaGetSymbolAddress((void**)&o3h, g_o3h); cudaGetSymbolAddress((void**)&o3l, g_o3l);
    cudaGetSymbolAddress((void**)&pph, g_pph); cudaGetSymbolAddress((void**)&ppl, g_ppl);
    cudaGetSymbolAddress((void**)&ath, g_ath); cudaGetSymbolAddress((void**)&atl, g_atl);
    cudaGetSymbolAddress((void**)&cxh, g_cxh); cudaGetSymbolAddress((void**)&cxl, g_cxl);

    bf16 *pqh = o3h,           *pql = o3l;
    bf16 *pkh = o3h + NBE,     *pkl = o3l + NBE;
    bf16 *vh  = o3h + 2 * NBE, *vl  = o3l + 2 * NBE;

    cudaFuncSetAttribute(gemm_nt_s<true>,  cudaFuncAttributeMaxDynamicSharedMemorySize, NT_SMEM);
    cudaFuncSetAttribute(gemm_nt_s<false>, cudaFuncAttributeMaxDynamicSharedMemorySize, NT_SMEM);
    cudaFuncSetAttribute(gemm_nn64_p<true>, cudaFuncAttributeMaxDynamicSharedMemorySize, NN_SMEM);

    // 1) pos emb + batched splits
    posemb_kernel<<<(SS * (DD / 2) + 255) / 256, 256>>>(peh, pel);
    split_in3<<<(3 * (NBE / 4) + 255) / 256, 256>>>(query, key, value, x3h, x3l);
    split_w5<<<(5 * (NWE / 4) + 255) / 256, 256>>>(Wq, Wk, Wv, Wp, Wo,
                                                   W3h, W3l, Wph, Wpl, Woh, Wol);

    // 2) QKV + P projections — ONE launch (z<3: q/k/v; z==3: P with 8 M-tiles)
    dim3 gqkvp(DD / 128, (BB * SS) / 128, 4);
    gemm_nt_s<true><<<gqkvp, 256, NT_SMEM>>>(x3h, x3l, W3h, W3l, nullptr, o3h, o3l,
                                             DD, DD, DD, DD,
                                             1, (long)NBE, 0, (long)NWE, 0, (long)NBE, 0,
                                             /*zAux=*/3, /*mAux=*/SS / 128,
                                             peh, pel, Wph, Wpl, pph, ppl,
                                             /*zSplit=*/1 << 30, nullptr, nullptr, nullptr,
                                             nullptr, nullptr);

    // 3) bias vectors (fused launch)
    bias_fused<<<(BB * HH * SS + HH * SS) / 8, 256>>>(pkh, pkl, pph, ppl, pu, pv, pbu, pbv);

    // 4) BOTH score GEMMs in ONE launch, with bias folded into epilogues:
    //    z<64 -> CS = q.k^T + bu[b,h,:]  ;  z>=64 -> C2 = q.p^T + bv[h,:]
    dim3 gsc(SS / 128, SS / 128, 2 * BB * HH);
    gemm_nt_s<false><<<gsc, 256, NT_SMEM>>>(pqh, pql, pkh, pkl, pcs, nullptr, nullptr,
                                            DKK, DD, DD, SS, HH,
                                            (long)SS * DD, DKK, (long)SS * DD, DKK,
                                            (long)HH * SS * SS, (long)SS * SS,
                                            -1, 0, nullptr, nullptr, nullptr, nullptr,
                                            nullptr, nullptr,
                                            /*zSplit=*/BB * HH, pph, ppl, pc2,
                                            pbu, pbv);

    // 5) rel-shift + softmax (biases already folded) -> attn bf16 hi/lo
    dim3 gsm(SS, HH, BB);
    softmax_combine<<<gsm, 256>>>(pcs, pc2, ath, atl);

    // 6) context = attn @ v per (b,h) — cp.async pipeline, ctx bf16 hi/lo out
    dim3 gav(1, SS / 128, BB * HH);
    gemm_nn64_p<true><<<gav, 256, NN_SMEM>>>(ath, atl, vh, vl, nullptr, cxh, cxl,
                                             SS, SS, DD, DD, HH,
                                             (long)HH * SS * SS, (long)SS * SS,
                                             (long)SS * DD, DKK, (long)SS * DD, DKK);

    // 7) output projection: out = ctx @ Wo^T (fp32 out, no bias)
    dim3 gout(DD / 128, (BB * SS) / 128, 1);
    gemm_nt_s<false><<<gout, 256, NT_SMEM>>>(cxh, cxl, Woh, Wol, out, nullptr, nullptr,
                                             DD, DD, DD, DD, 1, 0, 0, 0, 0, 0, 0,
                                             -1, 0, nullptr, nullptr, nullptr, nullptr,
                                             nullptr, nullptr,
                                             /*zSplit=*/1 << 30, nullptr, nullptr, nullptr,
                                             nullptr, nullptr);
}

// round 17
// speedup vs baseline: 1.0579x; 1.0579x over previous
#include <cuda_runtime.h>
#include <cuda_bf16.h>
#include <mma.h>
#include <math.h>

using namespace nvcuda;

#define BB 4
#define SS 1024
#define DD 1024
#define HH 16
#define DKK 64
#define NBE (BB * SS * DD)   // 4M elems
#define NWE (DD * DD)        // 1M elems

typedef __nv_bfloat16 bf16;

// ---------------- scratch (device globals) ----------------------------------
__device__ float g_cs [67108864];
__device__ float g_c2 [67108864];
__device__ float g_bu [BB * HH * SS];
__device__ float g_bv [HH * SS];
__device__ bf16 g_x3h[3 * NBE], g_x3l[3 * NBE];
__device__ bf16 g_W3h[3 * NWE], g_W3l[3 * NWE];
__device__ bf16 g_Wph[NWE], g_Wpl[NWE];
__device__ bf16 g_Woh[NWE], g_Wol[NWE];
__device__ bf16 g_peh[SS * DD], g_pel[SS * DD];
__device__ bf16 g_o3h[3 * NBE], g_o3l[3 * NBE];
__device__ bf16 g_pph[SS * DD], g_ppl[SS * DD];
__device__ bf16 g_ath[67108864], g_atl[67108864];
__device__ bf16 g_cxh[NBE], g_cxl[NBE];

__device__ __forceinline__ unsigned su32(const void* p) {
    return (unsigned)__cvta_generic_to_shared(p);
}
__device__ __forceinline__ void cp16(unsigned saddr, const void* g) {
    asm volatile("cp.async.cg.shared.global [%0], [%1], 16;" :: "r"(saddr), "l"(g));
}

// ---------------- batched elementwise splits ----------------------------------
__global__ void split_in3(const float* __restrict__ q, const float* __restrict__ k,
                          const float* __restrict__ v,
                          bf16* __restrict__ hi, bf16* __restrict__ lo) {
    const int n4 = NBE / 4;
    int i = blockIdx.x * blockDim.x + threadIdx.x;
    if (i >= 3 * n4) return;
    const float* src = (i < n4) ? q : (i < 2 * n4 ? k : v);
    int li = i - (i < n4 ? 0 : (i < 2 * n4 ? n4 : 2 * n4));
    float4 fv = ((const float4*)src)[li];
    float f[4] = {fv.x, fv.y, fv.z, fv.w};
    bf16 h[4], l[4];
    #pragma unroll
    for (int t = 0; t < 4; t++) {
        h[t] = __float2bfloat16(f[t]);
        l[t] = __float2bfloat16(f[t] - __bfloat162float(h[t]));
    }
    ((uint2*)hi)[i] = *(uint2*)h;
    ((uint2*)lo)[i] = *(uint2*)l;
}

__global__ void split_w5(const float* __restrict__ wq, const float* __restrict__ wk,
                         const float* __restrict__ wv, const float* __restrict__ wp,
                         const float* __restrict__ wo,
                         bf16* __restrict__ w3h, bf16* __restrict__ w3l,
                         bf16* __restrict__ wph, bf16* __restrict__ wpl,
                         bf16* __restrict__ woh, bf16* __restrict__ wol) {
    const int n4 = NWE / 4;
    int i = blockIdx.x * blockDim.x + threadIdx.x;
    if (i >= 5 * n4) return;
    int sel = i / n4, li = i - sel * n4;
    const float* src;  bf16* hi;  bf16* lo;  int oi;
    switch (sel) {
        case 0: src = wq; hi = w3h; lo = w3l; oi = li;          break;
        case 1: src = wk; hi = w3h; lo = w3l; oi = li + n4;     break;
        case 2: src = wv; hi = w3h; lo = w3l; oi = li + 2 * n4; break;
        case 3: src = wp; hi = wph; lo = wpl; oi = li;          break;
        default:src = wo; hi = woh; lo = wol; oi = li;          break;
    }
    float4 fv = ((const float4*)src)[li];
    float f[4] = {fv.x, fv.y, fv.z, fv.w};
    bf16 h[4], l[4];
    #pragma unroll
    for (int t = 0; t < 4; t++) {
        h[t] = __float2bfloat16(f[t]);
        l[t] = __float2bfloat16(f[t] - __bfloat162float(h[t]));
    }
    ((uint2*)hi)[oi] = *(uint2*)h;
    ((uint2*)lo)[oi] = *(uint2*)l;
}

// ---------------- pos emb -----------------------------------------------------
__global__ void posemb_kernel(bf16* __restrict__ peh, bf16* __restrict__ pel) {
    int idx = blockIdx.x * blockDim.x + threadIdx.x;
    if (idx >= SS * (DD / 2)) return;
    int j = idx / (DD / 2);
    int i = idx - j * (DD / 2);
    float t = (2.0f * (float)i) / (float)DD;
    float invf = expf(-t * 9.210340371976184f);
    float pos = (float)(SS - 1 - j);
    float s, c;
    sincosf(pos * invf, &s, &c);
    bf16 sh = __float2bfloat16(s);
    bf16 ch = __float2bfloat16(c);
    peh[j * DD + i]          = sh;
    pel[j * DD + i]          = __float2bfloat16(s - __bfloat162float(sh));
    peh[j * DD + i + DD / 2] = ch;
    pel[j * DD + i + DD / 2] = __float2bfloat16(c - __bfloat162float(ch));
}

// ---------------- fused bias vectors -------------------------------------------
__global__ void bias_fused(const bf16* __restrict__ kh, const bf16* __restrict__ kl,
                           const bf16* __restrict__ ph, const bf16* __restrict__ pl,
                           const float* __restrict__ u, const float* __restrict__ vb,
                           float* __restrict__ bu, float* __restrict__ bv) {
    int gw   = (blockIdx.x * blockDim.x + threadIdx.x) >> 5;
    int lane = threadIdx.x & 31;
    const int NBU = BB * HH * SS;
    if (gw >= NBU + HH * SS) return;
    const bf16 *sh, *sl; const float* w; long base; float* dst; int di;
    if (gw < NBU) {
        int kk = gw % SS;
        int h  = (gw / SS) % HH;
        int b  = gw / (SS * HH);
        sh = kh; sl = kl; w = u + h * DKK;
        base = ((long)b * SS + kk) * DD + h * DKK;
        dst = bu; di = gw;
    } else {
        int g2 = gw - NBU;
        int j = g2 % SS;
        int h = g2 / SS;
        sh = ph; sl = pl; w = vb + h * DKK;
        base = (long)j * DD + h * DKK;
        dst = bv; di = g2;
    }
    float x0 = __bfloat162float(sh[base + lane])      + __bfloat162float(sl[base + lane]);
    float x1 = __bfloat162float(sh[base + lane + 32]) + __bfloat162float(sl[base + lane + 32]);
    float s = x0 * w[lane] + x1 * w[lane + 32];
    #pragma unroll
    for (int o = 16; o; o >>= 1) s += __shfl_xor_sync(0xffffffffu, s, o);
    if (lane == 0) dst[di] = s;
}

// ---------------- NT GEMM, cp.async 3-stage pipeline (R10-validated) ---------
#define NT_ARR_E   (128 * 24)
#define NT_STAGE_E (4 * NT_ARR_E)
#define NT_SMEM    (3 * NT_STAGE_E * 2)  // 73728 bytes

template<bool SPLIT>
__global__ __launch_bounds__(256, 2) void gemm_nt_s(
    const bf16* __restrict__ Ahg, const bf16* __restrict__ Alg,
    const bf16* __restrict__ Bhg, const bf16* __restrict__ Blg,
    float* __restrict__ C, bf16* __restrict__ Ch, bf16* __restrict__ Cl,
    int K, int lda, int ldb, int ldc,
    int Hdim, long strAb, long strAh, long strBb, long strBh, long strCb, long strCh,
    int zAux, int mAux,
    const bf16* A2h, const bf16* A2l, const bf16* B2h, const bf16* B2l,
    bf16* C2h, bf16* C2l,
    int zSplit, const bf16* Bsh, const bf16* Bsl, float* Csf)
{
    int z = blockIdx.z;
    long coff;
    if (zAux >= 0 && z == zAux) {
        if (blockIdx.y >= mAux) return;
        Ahg = A2h;  Alg = A2l;  Bhg = B2h;  Blg = B2l;
        Ch  = C2h;  Cl  = C2l;  C = nullptr;
        coff = 0;
    } else {
        long sBb = strBb;
        if (z >= zSplit) {
            z -= zSplit;
            Bhg = Bsh;  Blg = Bsl;  C = Csf;
            sBb = 0;
        }
        int bb = z / Hdim, hh = z - bb * Hdim;
        Ahg += bb * strAb + hh * strAh;  Alg += bb * strAb + hh * strAh;
        Bhg += bb * sBb + hh * strBh;    Blg += bb * sBb + hh * strBh;
        coff = bb * strCb + hh * strCh;
    }

    extern __shared__ __align__(16) bf16 smem[];

    const int tid  = threadIdx.x;
    const int m0   = blockIdx.y * 128;
    const int n0   = blockIdx.x * 128;
    const int lrow = tid >> 1;
    const int lc8  = (tid & 1) * 8;
    const int w    = tid >> 5;
    const int wm   = w >> 2;
    const int wn   = w & 3;

    const bf16* ah = Ahg + (long)(m0 + lrow) * lda + lc8;
    const bf16* al = Alg + (long)(m0 + lrow) * lda + lc8;
    const bf16* bh = Bhg + (long)(n0 + lrow) * ldb + lc8;
    const bf16* bl = Blg + (long)(n0 + lrow) * ldb + lc8;

    const unsigned sbase = su32(smem) + (unsigned)(lrow * 24 + lc8) * 2u;

    wmma::fragment<wmma::accumulator, 16, 16, 16, float> acc[4][2];
    #pragma unroll
    for (int i = 0; i < 4; i++)
        #pragma unroll
        for (int j = 0; j < 2; j++) wmma::fill_fragment(acc[i][j], 0.0f);

    const int nt = K / 16;

    auto load_stage = [&](int buf, int kt) {
        const unsigned so = sbase + (unsigned)(buf * NT_STAGE_E) * 2u;
        const int k0 = kt * 16;
        cp16(so,                       ah + k0);
        cp16(so + NT_ARR_E * 2u,       al + k0);
        cp16(so + 2u * NT_ARR_E * 2u,  bh + k0);
        cp16(so + 3u * NT_ARR_E * 2u,  bl + k0);
        asm volatile("cp.async.commit_group;" ::: "memory");
    };

    load_stage(0, 0);
    if (nt > 1) load_stage(1, 1);
    if (nt > 2) load_stage(2, 2);

    for (int kt = 0; kt < nt; kt++) {
        const int buf = kt % 3;
        const int rem = nt - kt - 1;
        if (rem >= 2)      asm volatile("cp.async.wait_group 2;" ::: "memory");
        else if (rem == 1) asm volatile("cp.async.wait_group 1;" ::: "memory");
        else               asm volatile("cp.async.wait_group 0;" ::: "memory");
        __syncthreads();

        bf16* sc = smem + buf * NT_STAGE_E;
        {
            wmma::fragment<wmma::matrix_a, 16, 16, 16, bf16, wmma::row_major> fa[4];
            wmma::fragment<wmma::matrix_b, 16, 16, 16, bf16, wmma::col_major> fbh[2], fbl[2];
            #pragma unroll
            for (int i = 0; i < 4; i++)
                wmma::load_matrix_sync(fa[i], &sc[(wm * 64 + i * 16) * 24], 24);
            #pragma unroll
            for (int j = 0; j < 2; j++) {
                wmma::load_matrix_sync(fbh[j], &sc[2 * NT_ARR_E + (wn * 32 + j * 16) * 24], 24);
                wmma::load_matrix_sync(fbl[j], &sc[3 * NT_ARR_E + (wn * 32 + j * 16) * 24], 24);
            }
            #pragma unroll
            for (int i = 0; i < 4; i++)
                #pragma unroll
                for (int j = 0; j < 2; j++) {
                    wmma::mma_sync(acc[i][j], fa[i], fbh[j], acc[i][j]);
                    wmma::mma_sync(acc[i][j], fa[i], fbl[j], acc[i][j]);
                }
            #pragma unroll
            for (int i = 0; i < 4; i++)
                wmma::load_matrix_sync(fa[i], &sc[NT_ARR_E + (wm * 64 + i * 16) * 24], 24);
            #pragma unroll
            for (int i = 0; i < 4; i++)
                #pragma unroll
                for (int j = 0; j < 2; j++)
                    wmma::mma_sync(acc[i][j], fa[i], fbh[j], acc[i][j]);
        }
        __syncthreads();
        if (kt + 3 < nt) load_stage(buf, kt + 3);
    }

    if constexpr (!SPLIT) {
        float* Co = C + coff;
        #pragma unroll
        for (int i = 0; i < 4; i++)
            #pragma unroll
            for (int j = 0; j < 2; j++)
                wmma::store_matrix_sync(Co + (long)(m0 + wm * 64 + i * 16) * ldc + n0 + wn * 32 + j * 16,
                                        acc[i][j], ldc, wmma::mem_row_major);
    } else {
        float* stg = (float*)smem + w * 16 * 20;   // drained pipeline smem
        bf16* Hh = Ch + coff;
        bf16* Ll = Cl + coff;
        const int lane = tid & 31;
        const int rr  = lane >> 1;
        const int c8  = (lane & 1) * 8;
        #pragma unroll
        for (int i = 0; i < 4; i++)
            #pragma unroll
            for (int j = 0; j < 2; j++) {
                __syncwarp();
                wmma::store_matrix_sync(stg, acc[i][j], 20, wmma::mem_row_major);
                __syncwarp();
                bf16 hv[8], lv[8];
                #pragma unroll
                for (int e = 0; e < 8; e++) {
                    float v = stg[rr * 20 + c8 + e];
                    hv[e] = __float2bfloat16(v);
                    lv[e] = __float2bfloat16(v - __bfloat162float(hv[e]));
                }
                long off = (long)(m0 + wm * 64 + i * 16 + rr) * ldc + n0 + wn * 32 + j * 16 + c8;
                *(uint4*)(Hh + off) = *(uint4*)hv;
                *(uint4*)(Ll + off) = *(uint4*)lv;
            }
    }
}

// ---------------- NN GEMM N=64, cp.async 3-stage pipeline --------------------
#define NN_A_E     (128 * 24)
#define NN_B_E     (16 * 72)
#define NN_STAGE_E (2 * NN_A_E + 2 * NN_B_E)
#define NN_SMEM    (3 * NN_STAGE_E * 2)          // 50688 bytes

template<bool SPLIT>
__global__ __launch_bounds__(256, 2) void gemm_nn64_p(
    const bf16* __restrict__ Ahg, const bf16* __restrict__ Alg,
    const bf16* __restrict__ Bhg, const bf16* __restrict__ Blg,
    float* __restrict__ C, bf16* __restrict__ Ch, bf16* __restrict__ Cl,
    int K, int lda, int ldb, int ldc,
    int Hdim, long strAb, long strAh, long strBb, long strBh, long strCb, long strCh)
{
    int z  = blockIdx.z;
    int bb = z / Hdim, hh = z - bb * Hdim;
    Ahg += bb * strAb + hh * strAh;  Alg += bb * strAb + hh * strAh;
    Bhg += bb * strBb + hh * strBh;  Blg += bb * strBb + hh * strBh;
    long coff = bb * strCb + hh * strCh;

    extern __shared__ __align__(16) bf16 smem[];

    const int tid  = threadIdx.x;
    const int m0   = blockIdx.y * 128;
    const int lrow = tid >> 1;
    const int lc8  = (tid & 1) * 8;
    const int brow = tid >> 3;
    const int bc8  = (tid & 7) * 8;
    const int w    = tid >> 5;
    const int wm   = w >> 1;
    const int wn   = w & 1;

    const bf16* ah = Ahg + (long)(m0 + lrow) * lda + lc8;
    const bf16* al = Alg + (long)(m0 + lrow) * lda + lc8;
    const bf16* bh = Bhg + (long)brow * ldb + bc8;
    const bf16* bl = Blg + (long)brow * ldb + bc8;

    const unsigned saA = su32(smem) + (unsigned)(lrow * 24 + lc8) * 2u;
    const unsigned saB = su32(smem) + (unsigned)(2 * NN_A_E + brow * 72 + bc8) * 2u;
    const bool doB = (tid < 128);

    wmma::fragment<wmma::accumulator, 16, 16, 16, float> acc[2][2];
    #pragma unroll
    for (int i = 0; i < 2; i++)
        #pragma unroll
        for (int j = 0; j < 2; j++) wmma::fill_fragment(acc[i][j], 0.0f);

    const int nt = K / 16;

    auto load_stage = [&](int buf, int kt) {
        const unsigned off = (unsigned)(buf * NN_STAGE_E) * 2u;
        const long k0 = (long)kt * 16;
        cp16(saA + off,                 ah + k0);
        cp16(saA + off + NN_A_E * 2u,   al + k0);
        if (doB) {
            cp16(saB + off,               bh + k0 * ldb);
            cp16(saB + off + NN_B_E * 2u, bl + k0 * ldb);
        }
        asm volatile("cp.async.commit_group;" ::: "memory");
    };

    load_stage(0, 0);
    if (nt > 1) load_stage(1, 1);
    if (nt > 2) load_stage(2, 2);

    for (int kt = 0; kt < nt; kt++) {
        const int buf = kt % 3;
        const int rem = nt - kt - 1;
        if (rem >= 2)      asm volatile("cp.async.wait_group 2;" ::: "memory");
        else if (rem == 1) asm volatile("cp.async.wait_group 1;" ::: "memory");
        else               asm volatile("cp.async.wait_group 0;" ::: "memory");
        __syncthreads();

        bf16* sc  = smem + buf * NN_STAGE_E;
        bf16* scB = sc + 2 * NN_A_E;
        {
            wmma::fragment<wmma::matrix_a, 16, 16, 16, bf16, wmma::row_major> fa[2];
            wmma::fragment<wmma::matrix_b, 16, 16, 16, bf16, wmma::row_major> fbh[2], fbl[2];
            #pragma unroll
            for (int i = 0; i < 2; i++)
                wmma::load_matrix_sync(fa[i], &sc[(wm * 32 + i * 16) * 24], 24);
            #pragma unroll
            for (int j = 0; j < 2; j++) {
                wmma::load_matrix_sync(fbh[j], &scB[wn * 32 + j * 16], 72);
                wmma::load_matrix_sync(fbl[j], &scB[NN_B_E + wn * 32 + j * 16], 72);
            }
            #pragma unroll
            for (int i = 0; i < 2; i++)
                #pragma unroll
                for (int j = 0; j < 2; j++) {
                    wmma::mma_sync(acc[i][j], fa[i], fbh[j], acc[i][j]);
                    wmma::mma_sync(acc[i][j], fa[i], fbl[j], acc[i][j]);
                }
            #pragma unroll
            for (int i = 0; i < 2; i++)
                wmma::load_matrix_sync(fa[i], &sc[NN_A_E + (wm * 32 + i * 16) * 24], 24);
            #pragma unroll
            for (int i = 0; i < 2; i++)
                #pragma unroll
                for (int j = 0; j < 2; j++)
                    wmma::mma_sync(acc[i][j], fa[i], fbh[j], acc[i][j]);
        }
        __syncthreads();
        if (kt + 3 < nt) load_stage(buf, kt + 3);
    }

    if constexpr (!SPLIT) {
        float* Co = C + coff;
        #pragma unroll
        for (int i = 0; i < 2; i++)
            #pragma unroll
            for (int j = 0; j < 2; j++)
                wmma::store_matrix_sync(Co + (long)(m0 + wm * 32 + i * 16) * ldc + wn * 32 + j * 16,
                                        acc[i][j], ldc, wmma::mem_row_major);
    } else {
        float* stg = (float*)smem + w * 16 * 20;
        bf16* Hh = Ch + coff;
        bf16* Ll = Cl + coff;
        const int lane = tid & 31;
        const int rr  = lane >> 1;
        const int c8  = (lane & 1) * 8;
        #pragma unroll
        for (int i = 0; i < 2; i++)
            #pragma unroll
            for (int j = 0; j < 2; j++) {
                __syncwarp();
                wmma::store_matrix_sync(stg, acc[i][j], 20, wmma::mem_row_major);
                __syncwarp();
                bf16 hv[8], lv[8];
                #pragma unroll
                for (int e = 0; e < 8; e++) {
                    float v = stg[rr * 20 + c8 + e];
                    hv[e] = __float2bfloat16(v);
                    lv[e] = __float2bfloat16(v - __bfloat162float(hv[e]));
                }
                long off = (long)(m0 + wm * 32 + i * 16 + rr) * ldc + wn * 32 + j * 16 + c8;
                *(uint4*)(Hh + off) = *(uint4*)hv;
                *(uint4*)(Ll + off) = *(uint4*)lv;
            }
    }
}

// ---------------- shift + combine + softmax (vectorized mem ops) -------------
// Thread t handles 4 consecutive columns: float4 cs/bu loads, scalar c2/bv
// gathers (neighbor-coalesced), packed uint2 bf16 stores. Reduction structure
// identical to the R13/R15-validated version.
__global__ __launch_bounds__(256) void softmax_combine(
    const float* __restrict__ cs, const float* __restrict__ c2,
    const float* __restrict__ bu, const float* __restrict__ bv,
    bf16* __restrict__ ath, bf16* __restrict__ atl)
{
    const int q = blockIdx.x, h = blockIdx.y, b = blockIdx.z;
    const long base = ((long)(b * HH + h) * SS + q) * SS;
    const float* csrow = cs + base;
    const float* psq   = c2 + base;
    const int    q1    = (q + 1 < SS) ? (q + 1) : (SS - 1);
    const float* psq1  = c2 + ((long)(b * HH + h) * SS + q1) * SS;
    const float* burow = bu + (long)(b * HH + h) * SS;
    const float* bvrow = bv + (long)h * SS;

    const int tid = threadIdx.x;
    const int c0  = tid * 4;

    float4 cv = *(const float4*)(csrow + c0);
    float4 uv = *(const float4*)(burow + c0);
    float cva[4] = {cv.x + uv.x, cv.y + uv.y, cv.z + uv.z, cv.w + uv.w};

    float vals[4];
    float mx = -1e30f;
    #pragma unroll
    for (int e = 0; e < 4; e++) {
        int c = c0 + e;
        float ps;
        if (c <= q)            { int j = SS - 1 - q + c; ps = psq[j]  + bvrow[j]; }
        else if (c == q + 1)   { ps = 0.0f; }
        else                   { int j = c - q - 2;      ps = psq1[j] + bvrow[j]; }
        float s = (cva[e] + ps) * 0.125f;
        vals[e] = s;
        mx = fmaxf(mx, s);
    }

    __shared__ float red[8];
    #pragma unroll
    for (int o = 16; o; o >>= 1) mx = fmaxf(mx, __shfl_xor_sync(0xffffffffu, mx, o));
    if ((tid & 31) == 0) red[tid >> 5] = mx;
    __syncthreads();
    if (tid < 32) {
        float m = (tid < 8) ? red[tid] : -1e30f;
        #pragma unroll
        for (int o = 16; o; o >>= 1) m = fmaxf(m, __shfl_xor_sync(0xffffffffu, m, o));
        if (tid == 0) red[0] = m;
    }
    __syncthreads();
    mx = red[0];

    float sum = 0.0f;
    #pragma unroll
    for (int e = 0; e < 4; e++) { vals[e] = __expf(vals[e] - mx); sum += vals[e]; }

    __shared__ float red2[8];
    #pragma unroll
    for (int o = 16; o; o >>= 1) sum += __shfl_xor_sync(0xffffffffu, sum, o);
    if ((tid & 31) == 0) red2[tid >> 5] = sum;
    __syncthreads();
    if (tid < 32) {
        float s = (tid < 8) ? red2[tid] : 0.0f;
        #pragma unroll
        for (int o = 16; o; o >>= 1) s += __shfl_xor_sync(0xffffffffu, s, o);
        if (tid == 0) red2[0] = s;
    }
    __syncthreads();
    const float inv = 1.0f / red2[0];

    bf16 hv[4], lv[4];
    #pragma unroll
    for (int e = 0; e < 4; e++) {
        float p = vals[e] * inv;
        hv[e] = __float2bfloat16(p);
        lv[e] = __float2bfloat16(p - __bfloat162float(hv[e]));
    }
    *(uint2*)(ath + base + c0) = *(uint2*)hv;
    *(uint2*)(atl + base + c0) = *(uint2*)lv;
}

// ---------------- launch -------------------------------------------------------
extern "C" void kernel_launch(void* const* d_in, const int* in_sizes, int n_in,
                              void* d_out, int out_size)
{
    const float* query = (const float*)d_in[0];
    const float* key   = (const float*)d_in[1];
    const float* value = (const float*)d_in[2];
    // d_in[3] = mask (all-true; no-op)
    const float* Wq = (const float*)d_in[4];
    const float* Wk = (const float*)d_in[5];
    const float* Wv = (const float*)d_in[6];
    const float* Wp = (const float*)d_in[7];
    const float* Wo = (const float*)d_in[8];
    const float* pu = (const float*)d_in[9];
    const float* pv = (const float*)d_in[10];
    float* out = (float*)d_out;

    float *pcs, *pc2, *pbu, *pbv;
    cudaGetSymbolAddress((void**)&pcs,  g_cs);
    cudaGetSymbolAddress((void**)&pc2,  g_c2);
    cudaGetSymbolAddress((void**)&pbu,  g_bu);
    cudaGetSymbolAddress((void**)&pbv,  g_bv);

    bf16 *x3h,*x3l,*W3h,*W3l,*Wph,*Wpl,*Woh,*Wol,*peh,*pel,*o3h,*o3l,*pph,*ppl,*ath,*atl,*cxh,*cxl;
    cudaGetSymbolAddress((void**)&x3h, g_x3h); cudaGetSymbolAddress((void**)&x3l, g_x3l);
    cudaGetSymbolAddress((void**)&W3h, g_W3h); cudaGetSymbolAddress((void**)&W3l, g_W3l);
    cudaGetSymbolAddress((void**)&Wph, g_Wph); cudaGetSymbolAddress((void**)&Wpl, g_Wpl);
    cudaGetSymbolAddress((void**)&Woh, g_Woh); cudaGetSymbolAddress((void**)&Wol, g_Wol);
    cudaGetSymbolAddress((void**)&peh, g_peh); cudaGetSymbolAddress((void**)&pel, g_pel);
    cudaGetSymbolAddress((void**)&o3h, g_o3h); cudaGetSymbolAddress((void**)&o3l, g_o3l);
    cudaGetSymbolAddress((void**)&pph, g_pph); cudaGetSymbolAddress((void**)&ppl, g_ppl);
    cudaGetSymbolAddress((void**)&ath, g_ath); cudaGetSymbolAddress((void**)&atl, g_atl);
    cudaGetSymbolAddress((void**)&cxh, g_cxh); cudaGetSymbolAddress((void**)&cxl, g_cxl);

    bf16 *pqh = o3h,           *pql = o3l;
    bf16 *pkh = o3h + NBE,     *pkl = o3l + NBE;
    bf16 *vh  = o3h + 2 * NBE, *vl  = o3l + 2 * NBE;

    cudaFuncSetAttribute(gemm_nt_s<true>,  cudaFuncAttributeMaxDynamicSharedMemorySize, NT_SMEM);
    cudaFuncSetAttribute(gemm_nt_s<false>, cudaFuncAttributeMaxDynamicSharedMemorySize, NT_SMEM);
    cudaFuncSetAttribute(gemm_nn64_p<true>, cudaFuncAttributeMaxDynamicSharedMemorySize, NN_SMEM);

    // 1) pos emb + batched splits
    posemb_kernel<<<(SS * (DD / 2) + 255) / 256, 256>>>(peh, pel);
    split_in3<<<(3 * (NBE / 4) + 255) / 256, 256>>>(query, key, value, x3h, x3l);
    split_w5<<<(5 * (NWE / 4) + 255) / 256, 256>>>(Wq, Wk, Wv, Wp, Wo,
                                                   W3h, W3l, Wph, Wpl, Woh, Wol);

    // 2) QKV + P projections — ONE launch (z<3: q/k/v; z==3: P with 8 M-tiles)
    dim3 gqkvp(DD / 128, (BB * SS) / 128, 4);
    gemm_nt_s<true><<<gqkvp, 256, NT_SMEM>>>(x3h, x3l, W3h, W3l, nullptr, o3h, o3l,
                                             DD, DD, DD, DD,
                                             1, (long)NBE, 0, (long)NWE, 0, (long)NBE, 0,
                                             /*zAux=*/3, /*mAux=*/SS / 128,
                                             peh, pel, Wph, Wpl, pph, ppl,
                                             /*zSplit=*/1 << 30, nullptr, nullptr, nullptr);

    // 3) bias vectors (fused launch)
    bias_fused<<<(BB * HH * SS + HH * SS) / 8, 256>>>(pkh, pkl, pph, ppl, pu, pv, pbu, pbv);

    // 4) BOTH score GEMMs in ONE launch: z<64 -> CS=q.k^T ; z>=64 -> C2=q.p^T
    dim3 gsc(SS / 128, SS / 128, 2 * BB * HH);
    gemm_nt_s<false><<<gsc, 256, NT_SMEM>>>(pqh, pql, pkh, pkl, pcs, nullptr, nullptr,
                                            DKK, DD, DD, SS, HH,
                                            (long)SS * DD, DKK, (long)SS * DD, DKK,
                                            (long)HH * SS * SS, (long)SS * SS,
                                            -1, 0, nullptr, nullptr, nullptr, nullptr,
                                            nullptr, nullptr,
                                            /*zSplit=*/BB * HH, pph, ppl, pc2);

    // 5) rel-shift + bias combine + softmax -> attn bf16 hi/lo
    dim3 gsm(SS, HH, BB);
    softmax_combine<<<gsm, 256>>>(pcs, pc2, pbu, pbv, ath, atl);

    // 6) context = attn @ v per (b,h) — cp.async pipeline, ctx bf16 hi/lo out
    dim3 gav(1, SS / 128, BB * HH);
    gemm_nn64_p<true><<<gav, 256, NN_SMEM>>>(ath, atl, vh, vl, nullptr, cxh, cxl,
                                             SS, SS, DD, DD, HH,
                                             (long)HH * SS * SS, (long)SS * SS,
                                             (long)SS * DD, DKK, (long)SS * DD, DKK);

    // 7) output projection: out = ctx @ Wo^T (fp32 out)
    dim3 gout(DD / 128, (BB * SS) / 128, 1);
    gemm_nt_s<false><<<gout, 256, NT_SMEM>>>(cxh, cxl, Woh, Wol, out, nullptr, nullptr,
                                             DD, DD, DD, DD, 1, 0, 0, 0, 0, 0, 0,
                                             -1, 0, nullptr, nullptr, nullptr, nullptr,
                                             nullptr, nullptr,
                                             /*zSplit=*/1 << 30, nullptr, nullptr, nullptr);
}